// round 10
// baseline (speedup 1.0000x reference)
#include <cuda_runtime.h>
#include <cstdint>

// Problem: input (512, 2048, 7, 7) fp32 -> per row of 49: mean of top-4.
// Output: (512, 2048, 1, 1) = 1,048,576 floats.
//
// R9: R8 (one 256-row tile per CTA, 4096 CTAs, 4 resident/SM) + chunked DMA:
// the 50,176B tile is brought in as 8 cp.async.bulk chunks of 32 rows
// (6,272B) with 8 mbarriers. Warp w waits ONLY on chunk w, computes its 32
// rows, exits. Time-to-first-compute drops ~8x and each warp's compute
// overlaps the remaining chunks' DMA, de-phasing the CTA's memory and
// compute instead of all 8 warps stalling on the full tile.

#define THREADS      256
#define TILE_ROWS    256
#define ROW_LEN      49
#define TILE_FLOATS  (TILE_ROWS * ROW_LEN)   // 12544
#define TILE_BYTES   (TILE_FLOATS * 4)       // 50176
#define NCHUNK       8
#define CHUNK_ROWS   (TILE_ROWS / NCHUNK)    // 32
#define CHUNK_FLOATS (CHUNK_ROWS * ROW_LEN)  // 1568
#define CHUNK_BYTES  (CHUNK_FLOATS * 4)      // 6272

__device__ __forceinline__ void ce(float& x, float& y) {
    float hi = fmaxf(x, y);
    float lo = fminf(x, y);
    x = hi; y = lo;
}

__device__ __forceinline__ void sort4(float& a, float& b, float& c, float& d) {
    ce(a, b); ce(c, d); ce(a, c); ce(b, d); ce(b, c);
}

__device__ __forceinline__ void merge4(float& t0, float& t1, float& t2, float& t3,
                                       float c0, float c1, float c2, float c3) {
    float m0 = fmaxf(t0, c3);
    float m1 = fmaxf(t1, c2);
    float m2 = fmaxf(t2, c1);
    float m3 = fmaxf(t3, c0);
    ce(m0, m2); ce(m1, m3); ce(m0, m1); ce(m2, m3);
    t0 = m0; t1 = m1; t2 = m2; t3 = m3;
}

__device__ __forceinline__ void mbar_init(uint32_t a, uint32_t cnt) {
    asm volatile("mbarrier.init.shared.b64 [%0], %1;" :: "r"(a), "r"(cnt) : "memory");
}

__device__ __forceinline__ void mbar_expect_tx(uint32_t a, uint32_t bytes) {
    asm volatile("mbarrier.arrive.expect_tx.shared.b64 _, [%0], %1;"
                 :: "r"(a), "r"(bytes) : "memory");
}

__device__ __forceinline__ void mbar_wait(uint32_t a, uint32_t parity) {
    asm volatile(
        "{\n\t"
        ".reg .pred p;\n\t"
        "WAIT_%=:\n\t"
        "mbarrier.try_wait.parity.shared.b64 p, [%0], %1;\n\t"
        "@!p bra WAIT_%=;\n\t"
        "}"
        :: "r"(a), "r"(parity) : "memory");
}

__device__ __forceinline__ void bulk_copy(uint32_t smem_dst, const void* gmem_src,
                                          uint32_t bytes, uint32_t mbar) {
    asm volatile(
        "cp.async.bulk.shared::cta.global.mbarrier::complete_tx::bytes "
        "[%0], [%1], %2, [%3];"
        :: "r"(smem_dst), "l"(gmem_src), "r"(bytes), "r"(mbar) : "memory");
}

__global__ __launch_bounds__(THREADS)
void apool_topk4_kernel(const float* __restrict__ in, float* __restrict__ out) {
    extern __shared__ float s[];                 // TILE_FLOATS
    __shared__ __align__(8) uint64_t mbar_s[NCHUNK];

    const int tid  = threadIdx.x;
    const int wid  = tid >> 5;                   // 0..7 -> chunk id
    const uint32_t s_base = (uint32_t)__cvta_generic_to_shared(s);
    const uint32_t mb0    = (uint32_t)__cvta_generic_to_shared(&mbar_s[0]);
    const long long t = blockIdx.x;

    // ---- Init barriers + issue all chunk DMAs in order ----
    if (tid == 0) {
        #pragma unroll
        for (int c = 0; c < NCHUNK; c++)
            mbar_init(mb0 + 8u * c, 1);
        asm volatile("fence.proxy.async.shared::cta;" ::: "memory");
        const float* gsrc = in + t * TILE_FLOATS;
        #pragma unroll
        for (int c = 0; c < NCHUNK; c++) {
            mbar_expect_tx(mb0 + 8u * c, CHUNK_BYTES);
            bulk_copy(s_base + (uint32_t)c * CHUNK_BYTES,
                      gsrc + c * CHUNK_FLOATS, CHUNK_BYTES, mb0 + 8u * c);
        }
    }
    __syncthreads();          // barriers visible to all warps before waiting

    // ---- Each warp waits only for ITS chunk, then computes 32 rows ----
    mbar_wait(mb0 + 8u * wid, 0);

    const float* row = s + wid * CHUNK_FLOATS + (tid & 31) * ROW_LEN;

    float t0 = row[0], t1 = row[1], t2 = row[2], t3 = row[3];
    sort4(t0, t1, t2, t3);

    #pragma unroll
    for (int k = 1; k < 12; k++) {
        float c0 = row[4 * k + 0];
        float c1 = row[4 * k + 1];
        float c2 = row[4 * k + 2];
        float c3 = row[4 * k + 3];
        sort4(c0, c1, c2, c3);
        merge4(t0, t1, t2, t3, c0, c1, c2, c3);
    }
    float e = row[48];
    t3 = fmaxf(t3, e);
    ce(t2, t3); ce(t1, t2); ce(t0, t1);

    out[t * TILE_ROWS + wid * CHUNK_ROWS + (tid & 31)] =
        (t0 + t1 + t2 + t3) * 0.25f;
}

extern "C" void kernel_launch(void* const* d_in, const int* in_sizes, int n_in,
                              void* d_out, int out_size) {
    const float* in = (const float*)d_in[0];
    float* out = (float*)d_out;

    const int rows = out_size;                 // 1,048,576
    const int blocks = rows / TILE_ROWS;       // 4096, divides exactly
    const int smem = TILE_BYTES;               // 50,176 B -> 4 CTAs/SM

    cudaFuncSetAttribute(apool_topk4_kernel,
                         cudaFuncAttributeMaxDynamicSharedMemorySize, smem);
    apool_topk4_kernel<<<blocks, THREADS, smem>>>(in, out);
}

// round 11
// speedup vs baseline: 1.0132x; 1.0132x over previous
#include <cuda_runtime.h>
#include <cstdint>

// Problem: input (512, 2048, 7, 7) fp32 -> per row of 49: mean of top-4.
// Output: (512, 2048, 1, 1) = 1,048,576 floats.
//
// R10: fully warp-autonomous CTAs, 2x more CTA pipelines per SM.
// 8192 CTAs x 128 threads; tile = 128 rows (25,088 B smem -> 8-9 CTAs/SM).
// Each warp owns one 32-row chunk end-to-end: lane 0 inits a private
// mbarrier, fences, issues its own cp.async.bulk (6,272 B); the warp
// syncwarps, waits on ITS barrier only, computes its 32 rows (sort4 +
// bitonic merge), stores coalesced, exits. No __syncthreads, no serial
// thread-0 DMA issue, no cross-warp coupling at all.

#define THREADS      128
#define TILE_ROWS    128
#define ROW_LEN      49
#define TILE_FLOATS  (TILE_ROWS * ROW_LEN)   // 6272
#define TILE_BYTES   (TILE_FLOATS * 4)       // 25088
#define NCHUNK       4                       // one per warp
#define CHUNK_ROWS   32
#define CHUNK_FLOATS (CHUNK_ROWS * ROW_LEN)  // 1568
#define CHUNK_BYTES  (CHUNK_FLOATS * 4)      // 6272

__device__ __forceinline__ void ce(float& x, float& y) {
    float hi = fmaxf(x, y);
    float lo = fminf(x, y);
    x = hi; y = lo;
}

__device__ __forceinline__ void sort4(float& a, float& b, float& c, float& d) {
    ce(a, b); ce(c, d); ce(a, c); ce(b, d); ce(b, c);
}

__device__ __forceinline__ void merge4(float& t0, float& t1, float& t2, float& t3,
                                       float c0, float c1, float c2, float c3) {
    float m0 = fmaxf(t0, c3);
    float m1 = fmaxf(t1, c2);
    float m2 = fmaxf(t2, c1);
    float m3 = fmaxf(t3, c0);
    ce(m0, m2); ce(m1, m3); ce(m0, m1); ce(m2, m3);
    t0 = m0; t1 = m1; t2 = m2; t3 = m3;
}

__device__ __forceinline__ void mbar_init(uint32_t a, uint32_t cnt) {
    asm volatile("mbarrier.init.shared.b64 [%0], %1;" :: "r"(a), "r"(cnt) : "memory");
}

__device__ __forceinline__ void mbar_expect_tx(uint32_t a, uint32_t bytes) {
    asm volatile("mbarrier.arrive.expect_tx.shared.b64 _, [%0], %1;"
                 :: "r"(a), "r"(bytes) : "memory");
}

__device__ __forceinline__ void mbar_wait(uint32_t a, uint32_t parity) {
    asm volatile(
        "{\n\t"
        ".reg .pred p;\n\t"
        "WAIT_%=:\n\t"
        "mbarrier.try_wait.parity.shared.b64 p, [%0], %1;\n\t"
        "@!p bra WAIT_%=;\n\t"
        "}"
        :: "r"(a), "r"(parity) : "memory");
}

__device__ __forceinline__ void bulk_copy(uint32_t smem_dst, const void* gmem_src,
                                          uint32_t bytes, uint32_t mbar) {
    asm volatile(
        "cp.async.bulk.shared::cta.global.mbarrier::complete_tx::bytes "
        "[%0], [%1], %2, [%3];"
        :: "r"(smem_dst), "l"(gmem_src), "r"(bytes), "r"(mbar) : "memory");
}

__global__ __launch_bounds__(THREADS)
void apool_topk4_kernel(const float* __restrict__ in, float* __restrict__ out) {
    extern __shared__ float s[];                 // TILE_FLOATS
    __shared__ __align__(8) uint64_t mbar_s[NCHUNK];

    const int tid  = threadIdx.x;
    const int wid  = tid >> 5;                   // 0..3: warp == chunk
    const int lane = tid & 31;
    const uint32_t s_base = (uint32_t)__cvta_generic_to_shared(s);
    const uint32_t mbw    = (uint32_t)__cvta_generic_to_shared(&mbar_s[wid]);
    const long long t = blockIdx.x;

    // ---- Warp-private DMA: init own barrier, fence, issue own chunk ----
    if (lane == 0) {
        mbar_init(mbw, 1);
        asm volatile("fence.proxy.async.shared::cta;" ::: "memory");
        mbar_expect_tx(mbw, CHUNK_BYTES);
        bulk_copy(s_base + (uint32_t)wid * CHUNK_BYTES,
                  in + t * TILE_FLOATS + wid * CHUNK_FLOATS,
                  CHUNK_BYTES, mbw);
    }
    __syncwarp();
    mbar_wait(mbw, 0);

    // ---- Compute: one row per thread (stride 49 -> conflict-free) ----
    const float* row = s + wid * CHUNK_FLOATS + lane * ROW_LEN;

    float t0 = row[0], t1 = row[1], t2 = row[2], t3 = row[3];
    sort4(t0, t1, t2, t3);

    #pragma unroll
    for (int k = 1; k < 12; k++) {
        float c0 = row[4 * k + 0];
        float c1 = row[4 * k + 1];
        float c2 = row[4 * k + 2];
        float c3 = row[4 * k + 3];
        sort4(c0, c1, c2, c3);
        merge4(t0, t1, t2, t3, c0, c1, c2, c3);
    }
    float e = row[48];
    t3 = fmaxf(t3, e);
    ce(t2, t3); ce(t1, t2); ce(t0, t1);

    out[t * TILE_ROWS + wid * CHUNK_ROWS + lane] = (t0 + t1 + t2 + t3) * 0.25f;
}

extern "C" void kernel_launch(void* const* d_in, const int* in_sizes, int n_in,
                              void* d_out, int out_size) {
    const float* in = (const float*)d_in[0];
    float* out = (float*)d_out;

    const int rows = out_size;                 // 1,048,576
    const int blocks = rows / TILE_ROWS;       // 8192, divides exactly
    const int smem = TILE_BYTES;               // 25,088 B -> 8-9 CTAs/SM

    cudaFuncSetAttribute(apool_topk4_kernel,
                         cudaFuncAttributeMaxDynamicSharedMemorySize, smem);
    apool_topk4_kernel<<<blocks, THREADS, smem>>>(in, out);
}